// round 13
// baseline (speedup 1.0000x reference)
#include <cuda_runtime.h>
#include <cuda_fp16.h>
#include <cstdint>

#define BATCH 8
#define CIN   64
#define COUT  64
#define HH    112
#define WW    112
#define HWSZ  (HH*WW)

// ---------------- precomputed fp16 planes ----------------
__device__ __align__(128) __half g_x_h[BATCH * HH * WW * CIN];   // [b][y][x][c]
__device__ __align__(128) __half g_w_h[9 * COUT * CIN];          // [t][o][c]

// ================= fused prep (unchanged, passing) =================
#define PS 114

__global__ __launch_bounds__(128, 15)
void prep_kernel(const float* __restrict__ x, const float* __restrict__ w)
{
    __shared__ __align__(16) __half stile[CIN * PS];
    const int tid = threadIdx.x;
    const int bx  = blockIdx.x;
    const int b   = blockIdx.y;

    if (bx >= 224) {
        const int slot = (bx - 224) + 8 * b;
        #pragma unroll
        for (int j = 0; j < 5; j++) {
            int el = j * 128 + tid;
            if (el < 576) {
                int e = slot * 576 + el;
                int c = e & 63, o = (e >> 6) & 63, t = e >> 12;
                g_w_h[(t * COUT + o) * CIN + c] =
                    __float2half(w[o * (CIN * 9) + c * 9 + t]);
            }
        }
        return;
    }

    const int y    = bx >> 1;
    const int half = (bx & 1) * 56;
    const float* xb = x + ((size_t)b * CIN) * HWSZ + y * WW + half;

    #pragma unroll
    for (int k = 0; k < 8; k++) {
        int u   = k * 128 + tid;
        int c   = u >> 4;
        int sub = u & 15;
        if (sub < 14) {
            float4 v = *(const float4*)&xb[(size_t)c * HWSZ + sub * 4];
            __half2 h0 = __floats2half2_rn(v.x, v.y);
            __half2 h1 = __floats2half2_rn(v.z, v.w);
            *(__half2*)&stile[c * PS + sub * 4]     = h0;
            *(__half2*)&stile[c * PS + sub * 4 + 2] = h1;
        }
    }
    __syncthreads();

    const int cg = tid & 7;
    #pragma unroll
    for (int j = 0; j < 4; j++) {
        int xx = j * 16 + (tid >> 3);
        if (xx < 56) {
            __half h[8];
            #pragma unroll
            for (int k = 0; k < 8; k++)
                h[k] = stile[(cg * 8 + k) * PS + xx];
            *(uint4*)&g_x_h[((size_t)((b * HH + y) * WW) + half + xx) * CIN + cg * 8] =
                *(uint4*)h;
        }
    }
}

// ================= base-ISA async/MMA primitives =================
__device__ __forceinline__ uint32_t smem_u32(const void* p) {
    uint32_t a;
    asm("{ .reg .u64 t; cvta.to.shared.u64 t, %1; cvt.u32.u64 %0, t; }" : "=r"(a) : "l"(p));
    return a;
}
__device__ __forceinline__ void cp16(uint32_t dst, const void* src, uint32_t sz) {
    asm volatile("cp.async.cg.shared.global [%0], [%1], 16, %2;"
                 :: "r"(dst), "l"(src), "r"(sz) : "memory");
}
#define CP_COMMIT() asm volatile("cp.async.commit_group;" ::: "memory")
#define CP_WAIT0()  asm volatile("cp.async.wait_group 0;" ::: "memory")

__device__ __forceinline__ void ldmx4(uint32_t* r, uint32_t addr) {
    asm volatile("ldmatrix.sync.aligned.m8n8.x4.shared.b16 {%0,%1,%2,%3}, [%4];"
                 : "=r"(r[0]), "=r"(r[1]), "=r"(r[2]), "=r"(r[3]) : "r"(addr));
}
__device__ __forceinline__ void mma16816(float* c, const uint32_t* a,
                                         uint32_t b0, uint32_t b1) {
    asm volatile("mma.sync.aligned.m16n8k16.row.col.f32.f16.f16.f32 "
                 "{%0,%1,%2,%3}, {%4,%5,%6,%7}, {%8,%9}, {%0,%1,%2,%3};"
                 : "+f"(c[0]), "+f"(c[1]), "+f"(c[2]), "+f"(c[3])
                 : "r"(a[0]), "r"(a[1]), "r"(a[2]), "r"(a[3]), "r"(b0), "r"(b1));
}

// ================= main kernel: M=64 tiles, 5 CTAs/SM =================
// 128 threads (4 warps = 2m x 2n), warp tile 32 x 32.
// CTA = 8x8 output positions (all 64 outputs), grid (196, 8) = 1568 CTAs.
// smem: [0, 12800)   x tile: 100 rows (10x10) x 128B (XOR-swizzled)
//       [12800, 12928) zero row
//       [12928, 29312) B double buffer: 2 x 8KB
// epilogue reuses [0, 16896) as C[64][66] fp32.
#define X_OFF   0
#define Z_OFF   12800
#define B_OFF   12928
#define B_BUF   8192
#define SMEM_SZ 29312
#define NT      128

__global__ __launch_bounds__(NT, 5)
void rconv_mma_kernel(const int* __restrict__ mask, float* __restrict__ out)
{
    extern __shared__ __align__(128) char smem[];
    const uint32_t sb = smem_u32(smem);

    const int tid  = threadIdx.x;
    const int wid  = tid >> 5;
    const int lane = tid & 31;
    const int tile = blockIdx.x;            // 0..195
    const int b    = blockIdx.y;
    const int x0   = (tile % 14) * 8;
    const int y0   = (tile / 14) * 8;

    const int wm = wid & 1;                 // m-tile: 32 positions
    const int wn = wid >> 1;                // n-tile: 32 outputs
    const int m0 = wm * 32;
    const int n0 = wn * 32;

    if (tid < 32) ((float*)(smem + Z_OFF))[tid] = 0.0f;

    // ---- per-thread ldmatrix geometry ----
    const int ch      = lane >> 4;          // A k-half
    const int lanerow = lane & 15;
    int  rb[2], mk[2];
    #pragma unroll
    for (int mi = 0; mi < 2; mi++) {
        int p  = m0 + mi * 16 + lanerow;    // position 0..63
        int py = p >> 3, px = p & 7;
        rb[mi] = py * 10 + px;              // row in 10-wide staged tile
        mk[mi] = __ldg(&mask[(y0 + py) * WW + (x0 + px)]);
    }
    const int nlocal = (lane & 7) + ((lane >> 4) << 3);
    const int khalf  = (lane >> 3) & 1;
    int boff[2], bsw[2];
    #pragma unroll
    for (int ntp = 0; ntp < 2; ntp++) {     // 2 n16-tiles cover this warp's 32 outputs
        int orow = n0 + ntp * 16 + nlocal;
        boff[ntp] = orow * 128;
        bsw[ntp]  = orow & 7;
    }
    const uint32_t zaddr = sb + Z_OFF;

    // ---- prologue: stage x tile (10x10 rows) + B[0] ----
    for (int i = tid; i < 800; i += NT) {
        int r  = i >> 3;
        int j  = i & 7;
        int iy = r / 10, ix = r - iy * 10;
        int gy = y0 - 1 + iy, gx = x0 - 1 + ix;
        bool ok = (gy >= 0 && gy < HH && gx >= 0 && gx < WW);
        const __half* src = g_x_h +
            (ok ? (((size_t)((b * HH + gy) * WW + gx)) * CIN + j * 8) : 0);
        uint32_t dst = sb + X_OFF + r * 128 + ((j ^ (r & 7)) << 4);
        cp16(dst, src, ok ? 16u : 0u);
    }
    #pragma unroll
    for (int k = 0; k < 4; k++) {           // B[0]: 64 o x 8 j
        int i = k * NT + tid;
        int o = i >> 3, j = i & 7;
        const __half* src = g_w_h + ((0 * COUT + o) * CIN + j * 8);
        uint32_t dst = sb + B_OFF + o * 128 + ((j ^ (o & 7)) << 4);
        cp16(dst, src, 16u);
    }
    CP_COMMIT();

    float C[2][4][4];                       // [m16][n8][frag]
    #pragma unroll
    for (int mi = 0; mi < 2; mi++)
        #pragma unroll
        for (int nt = 0; nt < 4; nt++)
            #pragma unroll
            for (int k = 0; k < 4; k++) C[mi][nt][k] = 0.0f;

    int buf = 0;
    #pragma unroll 1
    for (int t = 0; t < 9; t++) {
        CP_WAIT0();
        __syncthreads();

        if (t < 8) {  // prefetch B[t+1] (overlaps compute)
            #pragma unroll
            for (int k = 0; k < 4; k++) {
                int i = k * NT + tid;
                int o = i >> 3, j = i & 7;
                const __half* src = g_w_h + (((t + 1) * COUT + o) * CIN + j * 8);
                uint32_t dst = sb + B_OFF + (buf ^ 1) * B_BUF + o * 128 + ((j ^ (o & 7)) << 4);
                cp16(dst, src, 16u);
            }
            CP_COMMIT();
        }

        const int kh   = t / 3;
        const int toff = t + kh * 7;         // kh*10 + kw
        int  r128[2], rm[2];
        bool msk[2];
        #pragma unroll
        for (int mi = 0; mi < 2; mi++) {
            int r = rb[mi] + toff;
            r128[mi] = r << 7;
            rm[mi]   = r & 7;
            msk[mi]  = (mk[mi] == t);
        }
        const uint32_t bb = sb + B_OFF + buf * B_BUF;

        #pragma unroll
        for (int kc = 0; kc < 4; kc++) {
            uint32_t A[2][4], Bv[2][4];
            #pragma unroll
            for (int mi = 0; mi < 2; mi++) {
                uint32_t sw = (uint32_t)((((kc << 1) | ch) ^ rm[mi]) << 4);
                uint32_t ah = msk[mi] ? zaddr : (sb + X_OFF + r128[mi] + sw);
                ldmx4(A[mi], ah);
            }
            #pragma unroll
            for (int ntp = 0; ntp < 2; ntp++) {
                uint32_t sw = (uint32_t)((((kc << 1) | khalf) ^ bsw[ntp]) << 4);
                ldmx4(Bv[ntp], bb + boff[ntp] + sw);
            }
            #pragma unroll
            for (int mi = 0; mi < 2; mi++)
                #pragma unroll
                for (int ntp = 0; ntp < 2; ntp++)
                    #pragma unroll
                    for (int s = 0; s < 2; s++)
                        mma16816(C[mi][ntp * 2 + s], A[mi],
                                 Bv[ntp][2 * s], Bv[ntp][2 * s + 1]);
        }
        buf ^= 1;
    }

    // ---- epilogue: C -> smem [m][o] (stride 66), then float4 stores ----
    __syncthreads();
    float* sC = (float*)smem;
    const int g   = lane >> 2;
    const int tg2 = (lane & 3) * 2;
    #pragma unroll
    for (int mi = 0; mi < 2; mi++)
        #pragma unroll
        for (int nt = 0; nt < 4; nt++) {
            int mrow = m0 + mi * 16 + g;
            int col  = n0 + nt * 8 + tg2;
            *(float2*)(sC + mrow * 66 + col)       = make_float2(C[mi][nt][0], C[mi][nt][1]);
            *(float2*)(sC + (mrow + 8) * 66 + col) = make_float2(C[mi][nt][2], C[mi][nt][3]);
        }
    __syncthreads();

    #pragma unroll
    for (int it = 0; it < 8; it++) {
        int idx = it * NT + tid;           // (o, py, q)
        int o   = idx >> 4;
        int rem = idx & 15;
        int py  = rem >> 1;
        int px  = (rem & 1) * 4;
        int mb  = py * 8 + px;
        float4 v;
        v.x = sC[(mb + 0) * 66 + o];
        v.y = sC[(mb + 1) * 66 + o];
        v.z = sC[(mb + 2) * 66 + o];
        v.w = sC[(mb + 3) * 66 + o];
        *(float4*)(out + ((size_t)(b * COUT + o)) * HWSZ + (y0 + py) * WW + (x0 + px)) = v;
    }
}

// ================= launch =================
extern "C" void kernel_launch(void* const* d_in, const int* in_sizes, int n_in,
                              void* d_out, int out_size)
{
    (void)in_sizes; (void)n_in; (void)out_size;
    const float* x    = (const float*)d_in[0];
    const float* w    = (const float*)d_in[1];
    const int*   mask = (const int*)d_in[2];
    float*       out  = (float*)d_out;

    prep_kernel<<<dim3(232, BATCH), 128>>>(x, w);

    cudaFuncSetAttribute(rconv_mma_kernel,
                         cudaFuncAttributeMaxDynamicSharedMemorySize, SMEM_SZ);
    rconv_mma_kernel<<<dim3(196, BATCH), NT, SMEM_SZ>>>(mask, out);
}